// round 9
// baseline (speedup 1.0000x reference)
#include <cuda_runtime.h>
#include <math.h>
#include <stdint.h>

#define HW 65536

// ---------------- device scratch ----------------
__device__ float g_w2c[8 * 16];
__device__ int   g_idx[16 * HW];
__device__ int   g_cnt[16];
__device__ float g_wB[2 * 2 * 9 * 32 * 64]; // [conv][coh][tap][col32][64] swizzled+paired
__device__ float g_fused[8ll * HW * 64];    // NHWC tf32, channel-permuted
__device__ float g_mid[8ll * HW * 64];      // NHWC tf32, channel-permuted

__constant__ int c_pj[6] = {0, 1, 1, 2, 2, 3};
__constant__ int c_pk[6] = {1, 0, 2, 1, 3, 2};

__device__ __forceinline__ float rtf32(float x) {
    uint32_t u;
    asm("cvt.rna.tf32.f32 %0, %1;" : "=r"(u) : "f"(x));
    return __uint_as_float(u);
}
__device__ __forceinline__ uint32_t smem_u32(const void* p) {
    uint32_t a;
    asm("{ .reg .u64 t; cvta.to.shared.u64 t, %1; cvt.u32.u64 %0, t; }" : "=r"(a) : "l"(p));
    return a;
}
__device__ __forceinline__ void mma_tf32(float* d, const uint32_t* a, const uint32_t* b) {
    asm volatile(
        "mma.sync.aligned.m16n8k8.row.col.f32.tf32.tf32.f32 "
        "{%0,%1,%2,%3}, {%4,%5,%6,%7}, {%8,%9}, {%0,%1,%2,%3};"
        : "+f"(d[0]), "+f"(d[1]), "+f"(d[2]), "+f"(d[3])
        : "r"(a[0]), "r"(a[1]), "r"(a[2]), "r"(a[3]), "r"(b[0]), "r"(b[1]));
}

// ---------------- setup ----------------
__global__ void setup_kernel(const float* __restrict__ extr,
                             const float* __restrict__ w1,
                             const float* __restrict__ w2) {
    int tid = threadIdx.x;
    if (tid < 16) g_cnt[tid] = 0;
    if (tid >= 64 && tid < 72) {
        const float* m = extr + (tid - 64) * 16;
        float inv[16];
        inv[0]  =  m[5]*m[10]*m[15] - m[5]*m[11]*m[14] - m[9]*m[6]*m[15] + m[9]*m[7]*m[14] + m[13]*m[6]*m[11] - m[13]*m[7]*m[10];
        inv[4]  = -m[4]*m[10]*m[15] + m[4]*m[11]*m[14] + m[8]*m[6]*m[15] - m[8]*m[7]*m[14] - m[12]*m[6]*m[11] + m[12]*m[7]*m[10];
        inv[8]  =  m[4]*m[9]*m[15]  - m[4]*m[11]*m[13] - m[8]*m[5]*m[15] + m[8]*m[7]*m[13] + m[12]*m[5]*m[11] - m[12]*m[7]*m[9];
        inv[12] = -m[4]*m[9]*m[14]  + m[4]*m[10]*m[13] + m[8]*m[5]*m[14] - m[8]*m[6]*m[13] - m[12]*m[5]*m[10] + m[12]*m[6]*m[9];
        inv[1]  = -m[1]*m[10]*m[15] + m[1]*m[11]*m[14] + m[9]*m[2]*m[15] - m[9]*m[3]*m[14] - m[13]*m[2]*m[11] + m[13]*m[3]*m[10];
        inv[5]  =  m[0]*m[10]*m[15] - m[0]*m[11]*m[14] - m[8]*m[2]*m[15] + m[8]*m[3]*m[14] + m[12]*m[2]*m[11] - m[12]*m[3]*m[10];
        inv[9]  = -m[0]*m[9]*m[15]  + m[0]*m[11]*m[13] + m[8]*m[1]*m[15] - m[8]*m[3]*m[13] - m[12]*m[1]*m[11] + m[12]*m[3]*m[9];
        inv[13] =  m[0]*m[9]*m[14]  - m[0]*m[10]*m[13] - m[8]*m[1]*m[14] + m[8]*m[2]*m[13] + m[12]*m[1]*m[10] - m[12]*m[2]*m[9];
        inv[2]  =  m[1]*m[6]*m[15]  - m[1]*m[7]*m[14]  - m[5]*m[2]*m[15] + m[5]*m[3]*m[14] + m[13]*m[2]*m[7]  - m[13]*m[3]*m[6];
        inv[6]  = -m[0]*m[6]*m[15]  + m[0]*m[7]*m[14]  + m[4]*m[2]*m[15] - m[4]*m[3]*m[14] - m[12]*m[2]*m[7]  + m[12]*m[3]*m[6];
        inv[10] =  m[0]*m[5]*m[15]  - m[0]*m[7]*m[13]  - m[4]*m[1]*m[15] + m[4]*m[3]*m[13] + m[12]*m[1]*m[7]  - m[12]*m[3]*m[5];
        inv[14] = -m[0]*m[5]*m[14]  + m[0]*m[6]*m[13]  + m[4]*m[1]*m[14] - m[4]*m[2]*m[13] - m[12]*m[1]*m[6]  + m[12]*m[2]*m[5];
        inv[3]  = -m[1]*m[6]*m[11]  + m[1]*m[7]*m[10]  + m[5]*m[2]*m[11] - m[5]*m[3]*m[10] - m[9]*m[2]*m[7]   + m[9]*m[3]*m[6];
        inv[7]  =  m[0]*m[6]*m[11]  - m[0]*m[7]*m[10]  - m[4]*m[2]*m[11] + m[4]*m[3]*m[10] + m[8]*m[2]*m[7]   - m[8]*m[3]*m[6];
        inv[11] = -m[0]*m[5]*m[11]  + m[0]*m[7]*m[9]   + m[4]*m[1]*m[11] - m[4]*m[3]*m[9]  - m[8]*m[1]*m[7]   + m[8]*m[3]*m[5];
        inv[15] =  m[0]*m[5]*m[10]  - m[0]*m[6]*m[9]   - m[4]*m[1]*m[10] + m[4]*m[2]*m[9]  + m[8]*m[1]*m[6]   - m[8]*m[2]*m[5];
        float det = m[0]*inv[0] + m[1]*inv[4] + m[2]*inv[8] + m[3]*inv[12];
        float rd = 1.0f / det;
        for (int n = 0; n < 16; n++) g_w2c[(tid - 64) * 16 + n] = inv[n] * rd;
    }
    // W layout: [conv][coh][tap][col 0..31][pofs], ci paired (ci, ci+4) + XOR swizzle.
    // conv0 column axis pre-permuted so its epilogue writes g_mid permuted.
    for (int i = tid; i < 73728; i += blockDim.x) {
        int c = i / 36864;
        int r = i - c * 36864;
        int tap = r >> 12;
        int q = r & 4095;
        int co = q >> 6, ci = q & 63;
        int coh = co >> 5;
        int col = co & 31;
        if (c == 0) col = (col & 24) | ((col & 3) << 1) | ((col >> 2) & 1);
        int k8 = ci >> 3, q4r = ci & 3, e = (ci >> 2) & 1;
        int pofs = (((k8 * 4 + q4r) ^ ((col & 7) * 4)) << 1) + e;
        int dst = ((c * 2 + coh) * 9 + tap) * 2048 + col * 64 + pofs;
        g_wB[dst] = rtf32((c ? w2 : w1)[(co * 64 + ci) * 9 + tap]);
    }
}

// ---------------- phase 1: projection + mask counts ----------------
__global__ void proj_kernel(const float* __restrict__ means,
                            const float* __restrict__ intrinsics) {
    int pi = blockIdx.y;
    int b = pi / 6, q = pi - b * 6;
    int j = c_pj[q], k = c_pk[q];
    int slot = (k < j) ? 0 : 1;
    int img = b * 4 + j;
    int pix = blockIdx.x * 256 + threadIdx.x;

    const float* m = means + ((long)img * HW + pix) * 3;
    float X = m[0], Y = m[1], Z = m[2];
    const float* w = g_w2c + (b * 4 + k) * 16;
    float c0 = w[0]*X + w[1]*Y + w[2]*Z  + w[3];
    float c1 = w[4]*X + w[5]*Y + w[6]*Z  + w[7];
    float c2 = w[8]*X + w[9]*Y + w[10]*Z + w[11];
    float dz = c2 + 1e-8f;
    float u0 = c0 / dz, u1 = c1 / dz, u2 = c2 / dz;
    const float* K = intrinsics + (b * 4 + k) * 9;
    float nx = K[0]*u0 + K[1]*u1 + K[2]*u2;
    float ny = K[3]*u0 + K[4]*u1 + K[5]*u2;
    bool mask = (nx >= 0.f) && (nx < 1.f) && (ny >= 0.f) && (ny < 1.f) && (c2 > 1e-8f);
    int px = (int)floorf(nx * 256.f);
    int py = (int)floorf(ny * 256.f);
    px = min(max(px, 0), 255);
    py = min(max(py, 0), 255);
    g_idx[(img * 2 + slot) * HW + pix] = mask ? (py * 256 + px) : -1;
    unsigned bal = __ballot_sync(0xFFFFFFFFu, mask);
    if ((threadIdx.x & 31) == 0)
        atomicAdd(&g_cnt[img * 2 + slot], __popc(bal));
}

// ---------------- phase 2: weighted fusion -> NHWC permuted tf32 ----------
__global__ void fuse_kernel(const float* __restrict__ feats) {
    const int img = blockIdx.y;
    const int j = img & 3;
    const int tid = threadIdx.x;
    const int pxl = tid & 63;
    const int chunk = tid >> 6;
    const int pix = (blockIdx.x << 6) + pxl;

    float s0 = 0.f, s1 = 0.f;
    int i0 = -1, i1 = -1;
    if (j > 0) {
        s0 = 0.1f * (float)g_cnt[img * 2 + 0] * (1.0f / 65536.f);
        i0 = g_idx[(img * 2 + 0) * HW + pix];
    }
    if (j < 3) {
        s1 = 0.1f * (float)g_cnt[img * 2 + 1] * (1.0f / 65536.f);
        i1 = g_idx[(img * 2 + 1) * HW + pix];
    }
    float rnorm = 1.f / (1.f + s0 + s1);

    const float4* sp = reinterpret_cast<const float4*>(feats + ((long)img * HW + pix) * 64 + (chunk << 4));
    float4 r[4];
#pragma unroll
    for (int q = 0; q < 4; q++) r[q] = sp[q];
    if (i0 >= 0) {
        const float4* gp = reinterpret_cast<const float4*>(feats + ((long)(img - 1) * HW + i0) * 64 + (chunk << 4));
#pragma unroll
        for (int q = 0; q < 4; q++) {
            float4 g = gp[q];
            r[q].x += s0 * g.x; r[q].y += s0 * g.y; r[q].z += s0 * g.z; r[q].w += s0 * g.w;
        }
    }
    if (i1 >= 0) {
        const float4* gp = reinterpret_cast<const float4*>(feats + ((long)(img + 1) * HW + i1) * 64 + (chunk << 4));
#pragma unroll
        for (int q = 0; q < 4; q++) {
            float4 g = gp[q];
            r[q].x += s1 * g.x; r[q].y += s1 * g.y; r[q].z += s1 * g.z; r[q].w += s1 * g.w;
        }
    }
#pragma unroll
    for (int q = 0; q < 4; q++) {
        r[q].x = rtf32(r[q].x * rnorm);
        r[q].y = rtf32(r[q].y * rnorm);
        r[q].z = rtf32(r[q].z * rnorm);
        r[q].w = rtf32(r[q].w * rnorm);
    }
    // permute: within each 8-group, channel c -> pos ((c&3)<<1)|((c>>2)&1)
    float4* op = reinterpret_cast<float4*>(g_fused + ((long)img * HW + pix) * 64 + (chunk << 4));
    float4 o0, o1, o2, o3;
    o0.x = r[0].x; o0.y = r[1].x; o0.z = r[0].y; o0.w = r[1].y;
    o1.x = r[0].z; o1.y = r[1].z; o1.z = r[0].w; o1.w = r[1].w;
    o2.x = r[2].x; o2.y = r[3].x; o2.z = r[2].y; o2.w = r[3].y;
    o3.x = r[2].z; o3.y = r[3].z; o3.z = r[2].w; o3.w = r[3].w;
    op[0] = o0; op[1] = o1; op[2] = o2; op[3] = o3;
}

// ---------------- conv: tf32 mma, input-row walk, paired float2 loads ------
#define GELU(v) (0.5f * (v) * (1.0f + erff((v) * 0.70710678118654752f)))

#define CONV_BODY(PH, STEPV) do {                                              \
    const int step_ = (STEPV);                                                 \
    { /* prefetch input row y0+step_ into slot (step_+1)&1 */                  \
        int rn = y0 + step_;                                                   \
        int okr = (rn < 256) ? 1 : 0;                                          \
        const char* rowp = (const char*)(inp + ((long)img * 256 + min(rn, 255)) * 16384); \
        uint32_t dstb = Xb + (uint32_t)(((step_ + 1) & 1) * 66048);            \
        for (int i = tid; i < 4128; i += 256) {                                \
            int p = i >> 4, c = i & 15;                                        \
            int gx = p - 1;                                                    \
            int ok = (okr && (unsigned)gx < 256u) ? 16 : 0;                    \
            const char* src = rowp + (uint32_t)min(max(gx, 0), 255) * 256u + (uint32_t)c * 16u; \
            uint32_t dst = dstb + (uint32_t)p * 256u + (uint32_t)((c ^ (p & 7)) << 4); \
            asm volatile("cp.async.cg.shared.global [%0], [%1], 16, %2;"       \
                         :: "r"(dst), "l"(src), "r"(ok));                      \
        }                                                                      \
        asm volatile("cp.async.commit_group;" ::: "memory");                   \
    }                                                                          \
    asm volatile("cp.async.wait_group 1;" ::: "memory");                       \
    __syncthreads();                                                           \
    {                                                                          \
        const float* X = Xf + (step_ & 1) * 16512;                             \
        _Pragma("unroll")                                                      \
        for (int k8 = 0; k8 < 8; k8++) {                                       \
            const int pofs = (k8 * 4 + q4) ^ (grp * 4);                        \
            uint32_t am[3][2][4];                                              \
            _Pragma("unroll")                                                  \
            for (int dxm = 0; dxm < 3; dxm++) {                                \
                const int ch = (((2 * k8 + qh) ^ ((grp + dxm) & 7)) << 2) + qe2; \
                const float* xp = X + (pb + grp + dxm) * 64 + ch;              \
                float2 t0 = *reinterpret_cast<const float2*>(xp);              \
                float2 t1 = *reinterpret_cast<const float2*>(xp + 512);        \
                float2 t2 = *reinterpret_cast<const float2*>(xp + 1024);       \
                float2 t3 = *reinterpret_cast<const float2*>(xp + 1536);       \
                am[dxm][0][0] = __float_as_uint(t0.x); am[dxm][0][2] = __float_as_uint(t0.y); \
                am[dxm][0][1] = __float_as_uint(t1.x); am[dxm][0][3] = __float_as_uint(t1.y); \
                am[dxm][1][0] = __float_as_uint(t2.x); am[dxm][1][2] = __float_as_uint(t2.y); \
                am[dxm][1][1] = __float_as_uint(t3.x); am[dxm][1][3] = __float_as_uint(t3.y); \
            }                                                                  \
            _Pragma("unroll")                                                  \
            for (int tr = 0; tr < 3; tr++) {                                   \
                const int S = ((PH) + 1 - tr + 3) % 3;                         \
                if (tr == 0 || step_ >= tr) {                                  \
                    _Pragma("unroll")                                          \
                    for (int dxm = 0; dxm < 3; dxm++) {                        \
                        const float2* wp = W2 + (tr * 3 + dxm) * 1024 + grp * 32 + pofs; \
                        uint32_t bb[4][2];                                     \
                        _Pragma("unroll")                                      \
                        for (int n = 0; n < 4; n++) {                          \
                            float2 t = wp[n * 256];                            \
                            bb[n][0] = __float_as_uint(t.x);                   \
                            bb[n][1] = __float_as_uint(t.y);                   \
                        }                                                      \
                        _Pragma("unroll")                                      \
                        for (int mt = 0; mt < 2; mt++)                         \
                            _Pragma("unroll")                                  \
                            for (int n = 0; n < 4; n++)                        \
                                mma_tf32(acc[S][mt][n], am[dxm][mt], bb[n]);   \
                    }                                                          \
                }                                                              \
            }                                                                  \
        }                                                                      \
    }                                                                          \
    if (step_ >= 2) {                                                          \
        const int E = ((PH) + 2) % 3;                                          \
        const int o = y0 + step_ - 2;                                          \
        _Pragma("unroll")                                                      \
        for (int mt = 0; mt < 2; mt++) {                                       \
            _Pragma("unroll")                                                  \
            for (int h = 0; h < 2; h++) {                                      \
                const int px = pb + mt * 16 + grp + h * 8;                     \
                float* op = outp + (((long)img * 256 + o) * 256 + px) * 64 + coh * 32; \
                _Pragma("unroll")                                              \
                for (int n = 0; n < 4; n++) {                                  \
                    const int co = n * 8 + q4 * 2;                             \
                    float2 v;                                                  \
                    v.x = acc[E][mt][n][h * 2 + 0] + bsm[co];                  \
                    v.y = acc[E][mt][n][h * 2 + 1] + bsm[co + 1];              \
                    if (MODE == 0) {                                           \
                        v.x = rtf32(GELU(v.x));                                \
                        v.y = rtf32(GELU(v.y));                                \
                    }                                                          \
                    *reinterpret_cast<float2*>(op + co) = v;                   \
                }                                                              \
            }                                                                  \
        }                                                                      \
        _Pragma("unroll")                                                      \
        for (int mt = 0; mt < 2; mt++)                                         \
            _Pragma("unroll")                                                  \
            for (int n = 0; n < 4; n++)                                        \
                _Pragma("unroll")                                              \
                for (int e = 0; e < 4; e++) acc[E][mt][n][e] = 0.f;            \
    }                                                                          \
    __syncthreads();                                                           \
} while (0)

template <int MODE>
__global__ __launch_bounds__(256, 1) void conv_mma(const float* __restrict__ bias,
                                                   float* __restrict__ d_outp) {
    extern __shared__ float sm[];
    float* Wf = sm;                    // 18432 floats
    float* Xf = sm + 18432;            // 2 x 16512 floats
    float* bsm = sm + 18432 + 33024;   // 32 floats

    const int tid = threadIdx.x;
    const int bx = blockIdx.x;
    const int img = bx / 18;
    const int coh = (bx / 9) & 1;
    const int seg = bx % 9;
    const int y0 = seg * 29;
    const int rows = (seg == 8) ? 24 : 29;

    const float* __restrict__ inp = (MODE == 0) ? g_fused : g_mid;
    float* __restrict__ outp = (MODE == 0) ? g_mid : d_outp;

    {
        const float4* ws = reinterpret_cast<const float4*>(g_wB + (MODE * 2 + coh) * 18432);
        float4* wd = reinterpret_cast<float4*>(Wf);
        for (int i = tid; i < 4608; i += 256) wd[i] = ws[i];
        if (tid < 32) {
            int dst = (MODE == 0) ? ((tid & 24) | ((tid & 3) << 1) | ((tid >> 2) & 1)) : tid;
            bsm[dst] = bias[coh * 32 + tid];
        }
    }

    const uint32_t Xb = smem_u32(Xf);
    const float2* W2 = reinterpret_cast<const float2*>(Wf);
    const int lane = tid & 31;
    const int grp = lane >> 2, q4 = lane & 3;
    const int pb = (tid >> 5) * 32;
    const int qe2 = (q4 & 1) * 2;
    const int qh = q4 >> 1;

    float acc[3][2][4][4];
#pragma unroll
    for (int s = 0; s < 3; s++)
#pragma unroll
        for (int mt = 0; mt < 2; mt++)
#pragma unroll
            for (int n = 0; n < 4; n++)
#pragma unroll
                for (int e = 0; e < 4; e++) acc[s][mt][n][e] = 0.f;

    // prologue: load strip r = y0-1 into slot 0
    {
        int rn = y0 - 1;
        int okr = (rn >= 0) ? 1 : 0;
        const char* rowp = (const char*)(inp + ((long)img * 256 + max(rn, 0)) * 16384);
        for (int i = tid; i < 4128; i += 256) {
            int p = i >> 4, c = i & 15;
            int gx = p - 1;
            int ok = (okr && (unsigned)gx < 256u) ? 16 : 0;
            const char* src = rowp + (uint32_t)min(max(gx, 0), 255) * 256u + (uint32_t)c * 16u;
            uint32_t dst = Xb + (uint32_t)p * 256u + (uint32_t)((c ^ (p & 7)) << 4);
            asm volatile("cp.async.cg.shared.global [%0], [%1], 16, %2;"
                         :: "r"(dst), "l"(src), "r"(ok));
        }
        asm volatile("cp.async.commit_group;" ::: "memory");
    }

    const int T = rows + 2;
    for (int s = 0; s < T; s += 3) {
        CONV_BODY(0, s);
        if (s + 1 < T) CONV_BODY(1, s + 1);
        if (s + 2 < T) CONV_BODY(2, s + 2);
    }
}

// ---------------- launch ----------------
extern "C" void kernel_launch(void* const* d_in, const int* in_sizes, int n_in,
                              void* d_out, int out_size) {
    const float* means      = (const float*)d_in[0];
    const float* gs_feats   = (const float*)d_in[2];
    const float* intrinsics = (const float*)d_in[3];
    const float* extrinsics = (const float*)d_in[4];
    const float* w1 = (const float*)d_in[5];
    const float* b1 = (const float*)d_in[6];
    const float* w2 = (const float*)d_in[7];
    const float* b2 = (const float*)d_in[8];
    float* out = (float*)d_out;

    const int smem = (18432 + 33024 + 32) * 4;  // 205,952 B
    cudaFuncSetAttribute(conv_mma<0>, cudaFuncAttributeMaxDynamicSharedMemorySize, smem);
    cudaFuncSetAttribute(conv_mma<1>, cudaFuncAttributeMaxDynamicSharedMemorySize, smem);

    setup_kernel<<<1, 256>>>(extrinsics, w1, w2);
    proj_kernel<<<dim3(256, 12), 256>>>(means, intrinsics);
    fuse_kernel<<<dim3(1024, 8), 256>>>(gs_feats);
    conv_mma<0><<<144, 256, smem>>>(b1, out);
    conv_mma<1><<<144, 256, smem>>>(b2, out);
}

// round 10
// speedup vs baseline: 1.7621x; 1.7621x over previous
#include <cuda_runtime.h>
#include <math.h>
#include <stdint.h>

#define HW 65536

// ---------------- device scratch ----------------
__device__ float g_w2c[8 * 16];
__device__ int   g_idx[16 * HW];
__device__ int   g_cnt[16];
__device__ float g_wB[2 * 2 * 9 * 32 * 64]; // [conv][coh][tap][col32][64] swizzled+paired
__device__ float g_fused[8ll * HW * 64];    // NHWC tf32
__device__ float g_mid[8ll * HW * 64];      // NHWC tf32

__constant__ int c_pj[6] = {0, 1, 1, 2, 2, 3};
__constant__ int c_pk[6] = {1, 0, 2, 1, 3, 2};

__device__ __forceinline__ float rtf32(float x) {
    uint32_t u;
    asm("cvt.rna.tf32.f32 %0, %1;" : "=r"(u) : "f"(x));
    return __uint_as_float(u);
}
__device__ __forceinline__ uint32_t smem_u32(const void* p) {
    uint32_t a;
    asm("{ .reg .u64 t; cvta.to.shared.u64 t, %1; cvt.u32.u64 %0, t; }" : "=r"(a) : "l"(p));
    return a;
}
__device__ __forceinline__ void mma_tf32(float* d, const uint32_t* a, const uint32_t* b) {
    asm volatile(
        "mma.sync.aligned.m16n8k8.row.col.f32.tf32.tf32.f32 "
        "{%0,%1,%2,%3}, {%4,%5,%6,%7}, {%8,%9}, {%0,%1,%2,%3};"
        : "+f"(d[0]), "+f"(d[1]), "+f"(d[2]), "+f"(d[3])
        : "r"(a[0]), "r"(a[1]), "r"(a[2]), "r"(a[3]), "r"(b[0]), "r"(b[1]));
}

// ---------------- setup ----------------
__global__ void setup_kernel(const float* __restrict__ extr,
                             const float* __restrict__ w1,
                             const float* __restrict__ w2) {
    int tid = threadIdx.x;
    if (tid < 16) g_cnt[tid] = 0;
    if (tid >= 64 && tid < 72) {
        const float* m = extr + (tid - 64) * 16;
        float inv[16];
        inv[0]  =  m[5]*m[10]*m[15] - m[5]*m[11]*m[14] - m[9]*m[6]*m[15] + m[9]*m[7]*m[14] + m[13]*m[6]*m[11] - m[13]*m[7]*m[10];
        inv[4]  = -m[4]*m[10]*m[15] + m[4]*m[11]*m[14] + m[8]*m[6]*m[15] - m[8]*m[7]*m[14] - m[12]*m[6]*m[11] + m[12]*m[7]*m[10];
        inv[8]  =  m[4]*m[9]*m[15]  - m[4]*m[11]*m[13] - m[8]*m[5]*m[15] + m[8]*m[7]*m[13] + m[12]*m[5]*m[11] - m[12]*m[7]*m[9];
        inv[12] = -m[4]*m[9]*m[14]  + m[4]*m[10]*m[13] + m[8]*m[5]*m[14] - m[8]*m[6]*m[13] - m[12]*m[5]*m[10] + m[12]*m[6]*m[9];
        inv[1]  = -m[1]*m[10]*m[15] + m[1]*m[11]*m[14] + m[9]*m[2]*m[15] - m[9]*m[3]*m[14] - m[13]*m[2]*m[11] + m[13]*m[3]*m[10];
        inv[5]  =  m[0]*m[10]*m[15] - m[0]*m[11]*m[14] - m[8]*m[2]*m[15] + m[8]*m[3]*m[14] + m[12]*m[2]*m[11] - m[12]*m[3]*m[10];
        inv[9]  = -m[0]*m[9]*m[15]  + m[0]*m[11]*m[13] + m[8]*m[1]*m[15] - m[8]*m[3]*m[13] - m[12]*m[1]*m[11] + m[12]*m[3]*m[9];
        inv[13] =  m[0]*m[9]*m[14]  - m[0]*m[10]*m[13] - m[8]*m[1]*m[14] + m[8]*m[2]*m[13] + m[12]*m[1]*m[10] - m[12]*m[2]*m[9];
        inv[2]  =  m[1]*m[6]*m[15]  - m[1]*m[7]*m[14]  - m[5]*m[2]*m[15] + m[5]*m[3]*m[14] + m[13]*m[2]*m[7]  - m[13]*m[3]*m[6];
        inv[6]  = -m[0]*m[6]*m[15]  + m[0]*m[7]*m[14]  + m[4]*m[2]*m[15] - m[4]*m[3]*m[14] - m[12]*m[2]*m[7]  + m[12]*m[3]*m[6];
        inv[10] =  m[0]*m[5]*m[15]  - m[0]*m[7]*m[13]  - m[4]*m[1]*m[15] + m[4]*m[3]*m[13] + m[12]*m[1]*m[7]  - m[12]*m[3]*m[5];
        inv[14] = -m[0]*m[5]*m[14]  + m[0]*m[6]*m[13]  + m[4]*m[1]*m[14] - m[4]*m[2]*m[13] - m[12]*m[1]*m[6]  + m[12]*m[2]*m[5];
        inv[3]  = -m[1]*m[6]*m[11]  + m[1]*m[7]*m[10]  + m[5]*m[2]*m[11] - m[5]*m[3]*m[10] - m[9]*m[2]*m[7]   + m[9]*m[3]*m[6];
        inv[7]  =  m[0]*m[6]*m[11]  - m[0]*m[7]*m[10]  - m[4]*m[2]*m[11] + m[4]*m[3]*m[10] + m[8]*m[2]*m[7]   - m[8]*m[3]*m[6];
        inv[11] = -m[0]*m[5]*m[11]  + m[0]*m[7]*m[9]   + m[4]*m[1]*m[11] - m[4]*m[3]*m[9]  - m[8]*m[1]*m[7]   + m[8]*m[3]*m[5];
        inv[15] =  m[0]*m[5]*m[10]  - m[0]*m[6]*m[9]   - m[4]*m[1]*m[10] + m[4]*m[2]*m[9]  + m[8]*m[1]*m[6]   - m[8]*m[2]*m[5];
        float det = m[0]*inv[0] + m[1]*inv[4] + m[2]*inv[8] + m[3]*inv[12];
        float rd = 1.0f / det;
        for (int n = 0; n < 16; n++) g_w2c[(tid - 64) * 16 + n] = inv[n] * rd;
    }
    // W layout: [conv][coh][tap][col 0..31][pofs], paired (ci, ci+4) + XOR swizzle
    for (int i = tid; i < 73728; i += blockDim.x) {
        int c = i / 36864;
        int r = i - c * 36864;
        int tap = r >> 12;
        int q = r & 4095;
        int co = q >> 6, ci = q & 63;
        int coh = co >> 5, col = co & 31;
        int k8 = ci >> 3, q4r = ci & 3, e = (ci >> 2) & 1;
        int pofs = (((k8 * 4 + q4r) ^ ((col & 7) * 4)) << 1) + e;
        int dst = ((c * 2 + coh) * 9 + tap) * 2048 + col * 64 + pofs;
        g_wB[dst] = rtf32((c ? w2 : w1)[(co * 64 + ci) * 9 + tap]);
    }
}

// ---------------- phase 1: projection + mask counts ----------------
__global__ void proj_kernel(const float* __restrict__ means,
                            const float* __restrict__ intrinsics) {
    int pi = blockIdx.y;
    int b = pi / 6, q = pi - b * 6;
    int j = c_pj[q], k = c_pk[q];
    int slot = (k < j) ? 0 : 1;
    int img = b * 4 + j;
    int pix = blockIdx.x * 256 + threadIdx.x;

    const float* m = means + ((long)img * HW + pix) * 3;
    float X = m[0], Y = m[1], Z = m[2];
    const float* w = g_w2c + (b * 4 + k) * 16;
    float c0 = w[0]*X + w[1]*Y + w[2]*Z  + w[3];
    float c1 = w[4]*X + w[5]*Y + w[6]*Z  + w[7];
    float c2 = w[8]*X + w[9]*Y + w[10]*Z + w[11];
    float dz = c2 + 1e-8f;
    float u0 = c0 / dz, u1 = c1 / dz, u2 = c2 / dz;
    const float* K = intrinsics + (b * 4 + k) * 9;
    float nx = K[0]*u0 + K[1]*u1 + K[2]*u2;
    float ny = K[3]*u0 + K[4]*u1 + K[5]*u2;
    bool mask = (nx >= 0.f) && (nx < 1.f) && (ny >= 0.f) && (ny < 1.f) && (c2 > 1e-8f);
    int px = (int)floorf(nx * 256.f);
    int py = (int)floorf(ny * 256.f);
    px = min(max(px, 0), 255);
    py = min(max(py, 0), 255);
    g_idx[(img * 2 + slot) * HW + pix] = mask ? (py * 256 + px) : -1;
    unsigned bal = __ballot_sync(0xFFFFFFFFu, mask);
    if ((threadIdx.x & 31) == 0)
        atomicAdd(&g_cnt[img * 2 + slot], __popc(bal));
}

// ---------------- phase 2: weighted fusion -> NHWC (tf32-rounded) ----------
__global__ void fuse_kernel(const float* __restrict__ feats) {
    const int img = blockIdx.y;
    const int j = img & 3;
    const int tid = threadIdx.x;
    const int pxl = tid & 63;
    const int chunk = tid >> 6;
    const int pix = (blockIdx.x << 6) + pxl;

    float s0 = 0.f, s1 = 0.f;
    int i0 = -1, i1 = -1;
    if (j > 0) {
        s0 = 0.1f * (float)g_cnt[img * 2 + 0] * (1.0f / 65536.f);
        i0 = g_idx[(img * 2 + 0) * HW + pix];
    }
    if (j < 3) {
        s1 = 0.1f * (float)g_cnt[img * 2 + 1] * (1.0f / 65536.f);
        i1 = g_idx[(img * 2 + 1) * HW + pix];
    }
    float rnorm = 1.f / (1.f + s0 + s1);

    const float4* sp = reinterpret_cast<const float4*>(feats + ((long)img * HW + pix) * 64 + (chunk << 4));
    float4 r[4];
#pragma unroll
    for (int q = 0; q < 4; q++) r[q] = sp[q];
    if (i0 >= 0) {
        const float4* gp = reinterpret_cast<const float4*>(feats + ((long)(img - 1) * HW + i0) * 64 + (chunk << 4));
#pragma unroll
        for (int q = 0; q < 4; q++) {
            float4 g = gp[q];
            r[q].x += s0 * g.x; r[q].y += s0 * g.y; r[q].z += s0 * g.z; r[q].w += s0 * g.w;
        }
    }
    if (i1 >= 0) {
        const float4* gp = reinterpret_cast<const float4*>(feats + ((long)(img + 1) * HW + i1) * 64 + (chunk << 4));
#pragma unroll
        for (int q = 0; q < 4; q++) {
            float4 g = gp[q];
            r[q].x += s1 * g.x; r[q].y += s1 * g.y; r[q].z += s1 * g.z; r[q].w += s1 * g.w;
        }
    }
    float4* op = reinterpret_cast<float4*>(g_fused + ((long)img * HW + pix) * 64 + (chunk << 4));
#pragma unroll
    for (int q = 0; q < 4; q++) {
        float4 v;
        v.x = rtf32(r[q].x * rnorm);
        v.y = rtf32(r[q].y * rnorm);
        v.z = rtf32(r[q].z * rnorm);
        v.w = rtf32(r[q].w * rnorm);
        op[q] = v;
    }
}

// ---------------- conv: tf32 mma, input-row walk (R6 base, 1 sync/row) ----
#define GELU(v) (0.5f * (v) * (1.0f + erff((v) * 0.70710678118654752f)))

#define CONV_BODY(PH, STEPV, ST) do {                                          \
    const int step_ = (STEPV);                                                 \
    asm volatile("cp.async.wait_group 0;" ::: "memory");                       \
    __syncthreads();                                                           \
    if (step_ <= rows) { /* issue row y0+step_ into buf (step_+1)&1 */         \
        int rn = y0 + step_;                                                   \
        int okr = (rn < 256) ? 1 : 0;                                          \
        const char* rowp = (const char*)(inp + ((long)img * 256 + min(rn, 255)) * 16384); \
        uint32_t dstb = Xb + (uint32_t)(((step_ + 1) & 1) * 66048);            \
        for (int i = tid; i < 4128; i += 256) {                                \
            int p = i >> 4, c = i & 15;                                        \
            int gx = p - 1;                                                    \
            int ok = (okr && (unsigned)gx < 256u) ? 16 : 0;                    \
            const char* src = rowp + (uint32_t)min(max(gx, 0), 255) * 256u + (uint32_t)c * 16u; \
            uint32_t dst = dstb + (uint32_t)p * 256u + (uint32_t)((c ^ (p & 7)) << 4); \
            asm volatile("cp.async.cg.shared.global [%0], [%1], 16, %2;"       \
                         :: "r"(dst), "l"(src), "r"(ok));                      \
        }                                                                      \
        asm volatile("cp.async.commit_group;" ::: "memory");                   \
    }                                                                          \
    {                                                                          \
        const float* X = Xf + (step_ & 1) * 16512;                             \
        _Pragma("unroll")                                                      \
        for (int k8 = 0; k8 < 8; k8++) {                                       \
            const int kc = k8 * 8;                                             \
            uint32_t a[3][2][4];                                               \
            _Pragma("unroll")                                                  \
            for (int dxm = 0; dxm < 3; dxm++) {                                \
                const int aswz = ((grp + dxm) & 7) * 4;                        \
                const int c0 = (kc + q4) ^ aswz, c1 = (kc + q4 + 4) ^ aswz;    \
                _Pragma("unroll")                                              \
                for (int mt = 0; mt < 2; mt++) {                               \
                    const float* xp = X + (pb + mt * 16 + grp + dxm) * 64;     \
                    a[dxm][mt][0] = __float_as_uint(xp[c0]);                   \
                    a[dxm][mt][1] = __float_as_uint(xp[512 + c0]);             \
                    a[dxm][mt][2] = __float_as_uint(xp[c1]);                   \
                    a[dxm][mt][3] = __float_as_uint(xp[512 + c1]);             \
                }                                                              \
            }                                                                  \
            _Pragma("unroll")                                                  \
            for (int tr = 0; tr < 3; tr++) {                                   \
                const int S = ((PH) + 1 - tr + 3) % 3;                         \
                if (ST || tr == 0 || step_ >= tr) {                            \
                    _Pragma("unroll")                                          \
                    for (int dxm = 0; dxm < 3; dxm++) {                        \
                        const float2* wp = W2 + (tr * 3 + dxm) * 1024 + grp * 32 + ((k8 * 4 + q4) ^ (grp * 4)); \
                        uint32_t bb[4][2];                                     \
                        _Pragma("unroll")                                      \
                        for (int n = 0; n < 4; n++) {                          \
                            float2 t = wp[n * 256];                            \
                            bb[n][0] = __float_as_uint(t.x);                   \
                            bb[n][1] = __float_as_uint(t.y);                   \
                        }                                                      \
                        _Pragma("unroll")                                      \
                        for (int mt = 0; mt < 2; mt++)                         \
                            _Pragma("unroll")                                  \
                            for (int n = 0; n < 4; n++)                        \
                                mma_tf32(acc[S][mt][n], a[dxm][mt], bb[n]);    \
                    }                                                          \
                }                                                              \
            }                                                                  \
        }                                                                      \
    }                                                                          \
    if (ST || step_ >= 2) {                                                    \
        const int E = ((PH) + 2) % 3;                                          \
        const int o = y0 + step_ - 2;                                          \
        _Pragma("unroll")                                                      \
        for (int mt = 0; mt < 2; mt++) {                                       \
            _Pragma("unroll")                                                  \
            for (int h = 0; h < 2; h++) {                                      \
                const int px = pb + mt * 16 + grp + h * 8;                     \
                float* op = outp + (((long)img * 256 + o) * 256 + px) * 64 + coh * 32; \
                _Pragma("unroll")                                              \
                for (int n = 0; n < 4; n++) {                                  \
                    const int co = n * 8 + q4 * 2;                             \
                    float2 v;                                                  \
                    v.x = acc[E][mt][n][h * 2 + 0] + bsm[co];                  \
                    v.y = acc[E][mt][n][h * 2 + 1] + bsm[co + 1];              \
                    if (MODE == 0) {                                           \
                        v.x = rtf32(GELU(v.x));                                \
                        v.y = rtf32(GELU(v.y));                                \
                    }                                                          \
                    *reinterpret_cast<float2*>(op + co) = v;                   \
                }                                                              \
            }                                                                  \
        }                                                                      \
        _Pragma("unroll")                                                      \
        for (int mt = 0; mt < 2; mt++)                                         \
            _Pragma("unroll")                                                  \
            for (int n = 0; n < 4; n++)                                        \
                _Pragma("unroll")                                              \
                for (int e = 0; e < 4; e++) acc[E][mt][n][e] = 0.f;            \
    }                                                                          \
} while (0)

template <int MODE>
__global__ __launch_bounds__(256, 1) void conv_mma(const float* __restrict__ bias,
                                                   float* __restrict__ d_outp) {
    extern __shared__ float sm[];
    float* Wf = sm;                    // 18432 floats
    float* Xf = sm + 18432;            // 2 x 16512 floats
    float* bsm = sm + 18432 + 33024;   // 32 floats

    const int tid = threadIdx.x;
    const int bx = blockIdx.x;
    const int img = bx / 18;
    const int coh = (bx / 9) & 1;
    const int seg = bx % 9;
    const int y0 = seg * 29;
    const int rows = (seg == 8) ? 24 : 29;

    const float* __restrict__ inp = (MODE == 0) ? g_fused : g_mid;
    float* __restrict__ outp = (MODE == 0) ? g_mid : d_outp;

    {
        const float4* ws = reinterpret_cast<const float4*>(g_wB + (MODE * 2 + coh) * 18432);
        float4* wd = reinterpret_cast<float4*>(Wf);
        for (int i = tid; i < 4608; i += 256) wd[i] = ws[i];
        if (tid < 32) bsm[tid] = bias[coh * 32 + tid];
    }

    const uint32_t Xb = smem_u32(Xf);
    const float2* W2 = reinterpret_cast<const float2*>(Wf);
    const int lane = tid & 31;
    const int grp = lane >> 2, q4 = lane & 3;
    const int pb = (tid >> 5) * 32;

    float acc[3][2][4][4];
#pragma unroll
    for (int s = 0; s < 3; s++)
#pragma unroll
        for (int mt = 0; mt < 2; mt++)
#pragma unroll
            for (int n = 0; n < 4; n++)
#pragma unroll
                for (int e = 0; e < 4; e++) acc[s][mt][n][e] = 0.f;

    // prologue: load strip r = y0-1 into buf 0
    {
        int rn = y0 - 1;
        int okr = (rn >= 0) ? 1 : 0;
        const char* rowp = (const char*)(inp + ((long)img * 256 + max(rn, 0)) * 16384);
        for (int i = tid; i < 4128; i += 256) {
            int p = i >> 4, c = i & 15;
            int gx = p - 1;
            int ok = (okr && (unsigned)gx < 256u) ? 16 : 0;
            const char* src = rowp + (uint32_t)min(max(gx, 0), 255) * 256u + (uint32_t)c * 16u;
            uint32_t dst = Xb + (uint32_t)p * 256u + (uint32_t)((c ^ (p & 7)) << 4);
            asm volatile("cp.async.cg.shared.global [%0], [%1], 16, %2;"
                         :: "r"(dst), "l"(src), "r"(ok));
        }
        asm volatile("cp.async.commit_group;" ::: "memory");
    }

    const int T = rows + 2;
    // edge steps 0,1 (partial taps, no epilogue)
    CONV_BODY(0, 0, 0);
    CONV_BODY(1, 1, 0);
    // steady steps 2..T-1, phase = s % 3, no conditionals
    int s = 2;
    for (; s + 2 < T; s += 3) {
        CONV_BODY(2, s, 1);
        CONV_BODY(0, s + 1, 1);
        CONV_BODY(1, s + 2, 1);
    }
    if (s < T)     { CONV_BODY(2, s, 1); }
    if (s + 1 < T) { CONV_BODY(0, s + 1, 1); }
}

// ---------------- launch ----------------
extern "C" void kernel_launch(void* const* d_in, const int* in_sizes, int n_in,
                              void* d_out, int out_size) {
    const float* means      = (const float*)d_in[0];
    const float* gs_feats   = (const float*)d_in[2];
    const float* intrinsics = (const float*)d_in[3];
    const float* extrinsics = (const float*)d_in[4];
    const float* w1 = (const float*)d_in[5];
    const float* b1 = (const float*)d_in[6];
    const float* w2 = (const float*)d_in[7];
    const float* b2 = (const float*)d_in[8];
    float* out = (float*)d_out;

    const int smem = (18432 + 33024 + 32) * 4;  // 205,952 B
    cudaFuncSetAttribute(conv_mma<0>, cudaFuncAttributeMaxDynamicSharedMemorySize, smem);
    cudaFuncSetAttribute(conv_mma<1>, cudaFuncAttributeMaxDynamicSharedMemorySize, smem);

    setup_kernel<<<1, 256>>>(extrinsics, w1, w2);
    proj_kernel<<<dim3(256, 12), 256>>>(means, intrinsics);
    fuse_kernel<<<dim3(1024, 8), 256>>>(gs_feats);
    conv_mma<0><<<144, 256, smem>>>(b1, out);
    conv_mma<1><<<144, 256, smem>>>(b2, out);
}

// round 11
// speedup vs baseline: 1.7684x; 1.0036x over previous
#include <cuda_runtime.h>
#include <math.h>
#include <stdint.h>

#define HW 65536

// ---------------- device scratch ----------------
__device__ float g_w2c[8 * 16];
__device__ int   g_idx[16 * HW];
__device__ int   g_cnt[16];
__device__ float g_wB[2 * 2 * 9 * 32 * 64]; // [conv][coh][tap][col32][64] swizzled+paired
__device__ float g_fused[8ll * HW * 64];    // NHWC tf32
__device__ float g_mid[8ll * HW * 64];      // NHWC tf32

__constant__ int c_pj[6] = {0, 1, 1, 2, 2, 3};
__constant__ int c_pk[6] = {1, 0, 2, 1, 3, 2};

__device__ __forceinline__ float rtf32(float x) {
    uint32_t u;
    asm("cvt.rna.tf32.f32 %0, %1;" : "=r"(u) : "f"(x));
    return __uint_as_float(u);
}
__device__ __forceinline__ uint32_t smem_u32(const void* p) {
    uint32_t a;
    asm("{ .reg .u64 t; cvta.to.shared.u64 t, %1; cvt.u32.u64 %0, t; }" : "=r"(a) : "l"(p));
    return a;
}
__device__ __forceinline__ void mma_tf32(float* d, const uint32_t* a, const uint32_t* b) {
    asm volatile(
        "mma.sync.aligned.m16n8k8.row.col.f32.tf32.tf32.f32 "
        "{%0,%1,%2,%3}, {%4,%5,%6,%7}, {%8,%9}, {%0,%1,%2,%3};"
        : "+f"(d[0]), "+f"(d[1]), "+f"(d[2]), "+f"(d[3])
        : "r"(a[0]), "r"(a[1]), "r"(a[2]), "r"(a[3]), "r"(b[0]), "r"(b[1]));
}

// ---------------- setup ----------------
__global__ void setup_kernel(const float* __restrict__ extr,
                             const float* __restrict__ w1,
                             const float* __restrict__ w2) {
    int tid = threadIdx.x;
    if (tid < 16) g_cnt[tid] = 0;
    if (tid >= 64 && tid < 72) {
        const float* m = extr + (tid - 64) * 16;
        float inv[16];
        inv[0]  =  m[5]*m[10]*m[15] - m[5]*m[11]*m[14] - m[9]*m[6]*m[15] + m[9]*m[7]*m[14] + m[13]*m[6]*m[11] - m[13]*m[7]*m[10];
        inv[4]  = -m[4]*m[10]*m[15] + m[4]*m[11]*m[14] + m[8]*m[6]*m[15] - m[8]*m[7]*m[14] - m[12]*m[6]*m[11] + m[12]*m[7]*m[10];
        inv[8]  =  m[4]*m[9]*m[15]  - m[4]*m[11]*m[13] - m[8]*m[5]*m[15] + m[8]*m[7]*m[13] + m[12]*m[5]*m[11] - m[12]*m[7]*m[9];
        inv[12] = -m[4]*m[9]*m[14]  + m[4]*m[10]*m[13] + m[8]*m[5]*m[14] - m[8]*m[6]*m[13] - m[12]*m[5]*m[10] + m[12]*m[6]*m[9];
        inv[1]  = -m[1]*m[10]*m[15] + m[1]*m[11]*m[14] + m[9]*m[2]*m[15] - m[9]*m[3]*m[14] - m[13]*m[2]*m[11] + m[13]*m[3]*m[10];
        inv[5]  =  m[0]*m[10]*m[15] - m[0]*m[11]*m[14] - m[8]*m[2]*m[15] + m[8]*m[3]*m[14] + m[12]*m[2]*m[11] - m[12]*m[3]*m[10];
        inv[9]  = -m[0]*m[9]*m[15]  + m[0]*m[11]*m[13] + m[8]*m[1]*m[15] - m[8]*m[3]*m[13] - m[12]*m[1]*m[11] + m[12]*m[3]*m[9];
        inv[13] =  m[0]*m[9]*m[14]  - m[0]*m[10]*m[13] - m[8]*m[1]*m[14] + m[8]*m[2]*m[13] + m[12]*m[1]*m[10] - m[12]*m[2]*m[9];
        inv[2]  =  m[1]*m[6]*m[15]  - m[1]*m[7]*m[14]  - m[5]*m[2]*m[15] + m[5]*m[3]*m[14] + m[13]*m[2]*m[7]  - m[13]*m[3]*m[6];
        inv[6]  = -m[0]*m[6]*m[15]  + m[0]*m[7]*m[14]  + m[4]*m[2]*m[15] - m[4]*m[3]*m[14] - m[12]*m[2]*m[7]  + m[12]*m[3]*m[6];
        inv[10] =  m[0]*m[5]*m[15]  - m[0]*m[7]*m[13]  - m[4]*m[1]*m[15] + m[4]*m[3]*m[13] + m[12]*m[1]*m[7]  - m[12]*m[3]*m[5];
        inv[14] = -m[0]*m[5]*m[14]  + m[0]*m[6]*m[13]  + m[4]*m[1]*m[14] - m[4]*m[2]*m[13] - m[12]*m[1]*m[6]  + m[12]*m[2]*m[5];
        inv[3]  = -m[1]*m[6]*m[11]  + m[1]*m[7]*m[10]  + m[5]*m[2]*m[11] - m[5]*m[3]*m[10] - m[9]*m[2]*m[7]   + m[9]*m[3]*m[6];
        inv[7]  =  m[0]*m[6]*m[11]  - m[0]*m[7]*m[10]  - m[4]*m[2]*m[11] + m[4]*m[3]*m[10] + m[8]*m[2]*m[7]   - m[8]*m[3]*m[6];
        inv[11] = -m[0]*m[5]*m[11]  + m[0]*m[7]*m[9]   + m[4]*m[1]*m[11] - m[4]*m[3]*m[9]  - m[8]*m[1]*m[7]   + m[8]*m[3]*m[5];
        inv[15] =  m[0]*m[5]*m[10]  - m[0]*m[6]*m[9]   - m[4]*m[1]*m[10] + m[4]*m[2]*m[9]  + m[8]*m[1]*m[6]   - m[8]*m[2]*m[5];
        float det = m[0]*inv[0] + m[1]*inv[4] + m[2]*inv[8] + m[3]*inv[12];
        float rd = 1.0f / det;
        for (int n = 0; n < 16; n++) g_w2c[(tid - 64) * 16 + n] = inv[n] * rd;
    }
    // W layout: [conv][coh][tap][col 0..31][pofs], paired (ci, ci+4) + XOR swizzle
    for (int i = tid; i < 73728; i += blockDim.x) {
        int c = i / 36864;
        int r = i - c * 36864;
        int tap = r >> 12;
        int q = r & 4095;
        int co = q >> 6, ci = q & 63;
        int coh = co >> 5, col = co & 31;
        int k8 = ci >> 3, q4r = ci & 3, e = (ci >> 2) & 1;
        int pofs = (((k8 * 4 + q4r) ^ ((col & 7) * 4)) << 1) + e;
        int dst = ((c * 2 + coh) * 9 + tap) * 2048 + col * 64 + pofs;
        g_wB[dst] = rtf32((c ? w2 : w1)[(co * 64 + ci) * 9 + tap]);
    }
}

// ---------------- phase 1: projection + mask counts ----------------
__global__ void proj_kernel(const float* __restrict__ means,
                            const float* __restrict__ intrinsics) {
    int pi = blockIdx.y;
    int b = pi / 6, q = pi - b * 6;
    int j = c_pj[q], k = c_pk[q];
    int slot = (k < j) ? 0 : 1;
    int img = b * 4 + j;
    int pix = blockIdx.x * 256 + threadIdx.x;

    const float* m = means + ((long)img * HW + pix) * 3;
    float X = m[0], Y = m[1], Z = m[2];
    const float* w = g_w2c + (b * 4 + k) * 16;
    float c0 = w[0]*X + w[1]*Y + w[2]*Z  + w[3];
    float c1 = w[4]*X + w[5]*Y + w[6]*Z  + w[7];
    float c2 = w[8]*X + w[9]*Y + w[10]*Z + w[11];
    float dz = c2 + 1e-8f;
    float u0 = c0 / dz, u1 = c1 / dz, u2 = c2 / dz;
    const float* K = intrinsics + (b * 4 + k) * 9;
    float nx = K[0]*u0 + K[1]*u1 + K[2]*u2;
    float ny = K[3]*u0 + K[4]*u1 + K[5]*u2;
    bool mask = (nx >= 0.f) && (nx < 1.f) && (ny >= 0.f) && (ny < 1.f) && (c2 > 1e-8f);
    int px = (int)floorf(nx * 256.f);
    int py = (int)floorf(ny * 256.f);
    px = min(max(px, 0), 255);
    py = min(max(py, 0), 255);
    g_idx[(img * 2 + slot) * HW + pix] = mask ? (py * 256 + px) : -1;
    unsigned bal = __ballot_sync(0xFFFFFFFFu, mask);
    if ((threadIdx.x & 31) == 0)
        atomicAdd(&g_cnt[img * 2 + slot], __popc(bal));
}

// ---------------- phase 2: weighted fusion -> NHWC (tf32-rounded) ----------
__global__ void fuse_kernel(const float* __restrict__ feats) {
    const int img = blockIdx.y;
    const int j = img & 3;
    const int tid = threadIdx.x;
    const int pxl = tid & 63;
    const int chunk = tid >> 6;
    const int pix = (blockIdx.x << 6) + pxl;

    float s0 = 0.f, s1 = 0.f;
    int i0 = -1, i1 = -1;
    if (j > 0) {
        s0 = 0.1f * (float)g_cnt[img * 2 + 0] * (1.0f / 65536.f);
        i0 = g_idx[(img * 2 + 0) * HW + pix];
    }
    if (j < 3) {
        s1 = 0.1f * (float)g_cnt[img * 2 + 1] * (1.0f / 65536.f);
        i1 = g_idx[(img * 2 + 1) * HW + pix];
    }
    float rnorm = 1.f / (1.f + s0 + s1);

    const float4* sp = reinterpret_cast<const float4*>(feats + ((long)img * HW + pix) * 64 + (chunk << 4));
    float4 r[4];
#pragma unroll
    for (int q = 0; q < 4; q++) r[q] = sp[q];
    if (i0 >= 0) {
        const float4* gp = reinterpret_cast<const float4*>(feats + ((long)(img - 1) * HW + i0) * 64 + (chunk << 4));
#pragma unroll
        for (int q = 0; q < 4; q++) {
            float4 g = gp[q];
            r[q].x += s0 * g.x; r[q].y += s0 * g.y; r[q].z += s0 * g.z; r[q].w += s0 * g.w;
        }
    }
    if (i1 >= 0) {
        const float4* gp = reinterpret_cast<const float4*>(feats + ((long)(img + 1) * HW + i1) * 64 + (chunk << 4));
#pragma unroll
        for (int q = 0; q < 4; q++) {
            float4 g = gp[q];
            r[q].x += s1 * g.x; r[q].y += s1 * g.y; r[q].z += s1 * g.z; r[q].w += s1 * g.w;
        }
    }
    float4* op = reinterpret_cast<float4*>(g_fused + ((long)img * HW + pix) * 64 + (chunk << 4));
#pragma unroll
    for (int q = 0; q < 4; q++) {
        float4 v;
        v.x = rtf32(r[q].x * rnorm);
        v.y = rtf32(r[q].y * rnorm);
        v.z = rtf32(r[q].z * rnorm);
        v.w = rtf32(r[q].w * rnorm);
        op[q] = v;
    }
}

// ---------------- conv: tf32 mma, input-row walk, 16 warps ----------------
// CTA = (img, coh, y-seg), 512 threads = 8 px-groups x 2 co-groups.
// Warp tile 32px x 16co (mt=2, n=2). R6 body structure.
#define GELU(v) (0.5f * (v) * (1.0f + erff((v) * 0.70710678118654752f)))

#define CONV_BODY(PH, STEPV) do {                                              \
    const int step_ = (STEPV);                                                 \
    { /* prefetch input row y0+step_ into slot (step_+1)&1 */                  \
        int rn = y0 + step_;                                                   \
        int okr = (rn < 256) ? 1 : 0;                                          \
        const char* rowp = (const char*)(inp + ((long)img * 256 + min(rn, 255)) * 16384); \
        uint32_t dstb = Xb + (uint32_t)(((step_ + 1) & 1) * 66048);            \
        for (int i = tid; i < 4128; i += 512) {                                \
            int p = i >> 4, c = i & 15;                                        \
            int gx = p - 1;                                                    \
            int ok = (okr && (unsigned)gx < 256u) ? 16 : 0;                    \
            const char* src = rowp + (uint32_t)min(max(gx, 0), 255) * 256u + (uint32_t)c * 16u; \
            uint32_t dst = dstb + (uint32_t)p * 256u + (uint32_t)((c ^ (p & 7)) << 4); \
            asm volatile("cp.async.cg.shared.global [%0], [%1], 16, %2;"       \
                         :: "r"(dst), "l"(src), "r"(ok));                      \
        }                                                                      \
        asm volatile("cp.async.commit_group;" ::: "memory");                   \
    }                                                                          \
    asm volatile("cp.async.wait_group 1;" ::: "memory");                       \
    __syncthreads();                                                           \
    {                                                                          \
        const float* X = Xf + (step_ & 1) * 16512;                             \
        _Pragma("unroll")                                                      \
        for (int k8 = 0; k8 < 8; k8++) {                                       \
            const int kc = k8 * 8;                                             \
            uint32_t a[3][2][4];                                               \
            _Pragma("unroll")                                                  \
            for (int dxm = 0; dxm < 3; dxm++) {                                \
                const int aswz = ((grp + dxm) & 7) * 4;                        \
                const int c0 = (kc + q4) ^ aswz, c1 = (kc + q4 + 4) ^ aswz;    \
                _Pragma("unroll")                                              \
                for (int mt = 0; mt < 2; mt++) {                               \
                    const float* xp = X + (pb + mt * 16 + grp + dxm) * 64;     \
                    a[dxm][mt][0] = __float_as_uint(xp[c0]);                   \
                    a[dxm][mt][1] = __float_as_uint(xp[512 + c0]);             \
                    a[dxm][mt][2] = __float_as_uint(xp[c1]);                   \
                    a[dxm][mt][3] = __float_as_uint(xp[512 + c1]);             \
                }                                                              \
            }                                                                  \
            _Pragma("unroll")                                                  \
            for (int tr = 0; tr < 3; tr++) {                                   \
                const int S = ((PH) + 1 - tr + 3) % 3;                         \
                if (tr == 0 || step_ >= tr) {                                  \
                    _Pragma("unroll")                                          \
                    for (int dxm = 0; dxm < 3; dxm++) {                        \
                        const float2* wp = W2 + (tr * 3 + dxm) * 1024 + coq * 512 + grp * 32 + ((kc / 2 + q4) ^ (grp * 4)); \
                        uint32_t bb[2][2];                                     \
                        _Pragma("unroll")                                      \
                        for (int n = 0; n < 2; n++) {                          \
                            float2 t = wp[n * 256];                            \
                            bb[n][0] = __float_as_uint(t.x);                   \
                            bb[n][1] = __float_as_uint(t.y);                   \
                        }                                                      \
                        _Pragma("unroll")                                      \
                        for (int mt = 0; mt < 2; mt++)                         \
                            _Pragma("unroll")                                  \
                            for (int n = 0; n < 2; n++)                        \
                                mma_tf32(acc[S][mt][n], a[dxm][mt], bb[n]);    \
                    }                                                          \
                }                                                              \
            }                                                                  \
        }                                                                      \
    }                                                                          \
    if (step_ >= 2) {                                                          \
        const int E = ((PH) + 2) % 3;                                          \
        const int o = y0 + step_ - 2;                                          \
        _Pragma("unroll")                                                      \
        for (int mt = 0; mt < 2; mt++) {                                       \
            _Pragma("unroll")                                                  \
            for (int h = 0; h < 2; h++) {                                      \
                const int px = pb + mt * 16 + grp + h * 8;                     \
                float* op = outp + (((long)img * 256 + o) * 256 + px) * 64 + coh * 32; \
                _Pragma("unroll")                                              \
                for (int n = 0; n < 2; n++) {                                  \
                    const int co = coq * 16 + n * 8 + q4 * 2;                  \
                    float2 v;                                                  \
                    v.x = acc[E][mt][n][h * 2 + 0] + bsm[co];                  \
                    v.y = acc[E][mt][n][h * 2 + 1] + bsm[co + 1];              \
                    if (MODE == 0) {                                           \
                        v.x = rtf32(GELU(v.x));                                \
                        v.y = rtf32(GELU(v.y));                                \
                    }                                                          \
                    *reinterpret_cast<float2*>(op + co) = v;                   \
                }                                                              \
            }                                                                  \
        }                                                                      \
        _Pragma("unroll")                                                      \
        for (int mt = 0; mt < 2; mt++)                                         \
            _Pragma("unroll")                                                  \
            for (int n = 0; n < 2; n++)                                        \
                _Pragma("unroll")                                              \
                for (int e = 0; e < 4; e++) acc[E][mt][n][e] = 0.f;            \
    }                                                                          \
    __syncthreads();                                                           \
} while (0)

template <int MODE>
__global__ __launch_bounds__(512, 1) void conv_mma(const float* __restrict__ bias,
                                                   float* __restrict__ d_outp) {
    extern __shared__ float sm[];
    float* Wf = sm;                    // 18432 floats
    float* Xf = sm + 18432;            // 2 x 16512 floats
    float* bsm = sm + 18432 + 33024;   // 32 floats

    const int tid = threadIdx.x;
    const int bx = blockIdx.x;
    const int img = bx / 18;
    const int coh = (bx / 9) & 1;
    const int seg = bx % 9;
    const int y0 = seg * 29;
    const int rows = (seg == 8) ? 24 : 29;

    const float* __restrict__ inp = (MODE == 0) ? g_fused : g_mid;
    float* __restrict__ outp = (MODE == 0) ? g_mid : d_outp;

    {
        const float4* ws = reinterpret_cast<const float4*>(g_wB + (MODE * 2 + coh) * 18432);
        float4* wd = reinterpret_cast<float4*>(Wf);
        for (int i = tid; i < 4608; i += 512) wd[i] = ws[i];
        if (tid < 32) bsm[tid] = bias[coh * 32 + tid];
    }

    const uint32_t Xb = smem_u32(Xf);
    const float2* W2 = reinterpret_cast<const float2*>(Wf);
    const int lane = tid & 31;
    const int wrp = tid >> 5;
    const int grp = lane >> 2, q4 = lane & 3;
    const int pxq = wrp & 7, coq = wrp >> 3;
    const int pb = pxq * 32;

    float acc[3][2][2][4];
#pragma unroll
    for (int s = 0; s < 3; s++)
#pragma unroll
        for (int mt = 0; mt < 2; mt++)
#pragma unroll
            for (int n = 0; n < 2; n++)
#pragma unroll
                for (int e = 0; e < 4; e++) acc[s][mt][n][e] = 0.f;

    // prologue: load strip r = y0-1 into buf 0
    {
        int rn = y0 - 1;
        int okr = (rn >= 0) ? 1 : 0;
        const char* rowp = (const char*)(inp + ((long)img * 256 + max(rn, 0)) * 16384);
        for (int i = tid; i < 4128; i += 512) {
            int p = i >> 4, c = i & 15;
            int gx = p - 1;
            int ok = (okr && (unsigned)gx < 256u) ? 16 : 0;
            const char* src = rowp + (uint32_t)min(max(gx, 0), 255) * 256u + (uint32_t)c * 16u;
            uint32_t dst = Xb + (uint32_t)p * 256u + (uint32_t)((c ^ (p & 7)) << 4);
            asm volatile("cp.async.cg.shared.global [%0], [%1], 16, %2;"
                         :: "r"(dst), "l"(src), "r"(ok));
        }
        asm volatile("cp.async.commit_group;" ::: "memory");
    }

    const int T = rows + 2;
    for (int s = 0; s < T; s += 3) {
        CONV_BODY(0, s);
        if (s + 1 < T) CONV_BODY(1, s + 1);
        if (s + 2 < T) CONV_BODY(2, s + 2);
    }
}

// ---------------- launch ----------------
extern "C" void kernel_launch(void* const* d_in, const int* in_sizes, int n_in,
                              void* d_out, int out_size) {
    const float* means      = (const float*)d_in[0];
    const float* gs_feats   = (const float*)d_in[2];
    const float* intrinsics = (const float*)d_in[3];
    const float* extrinsics = (const float*)d_in[4];
    const float* w1 = (const float*)d_in[5];
    const float* b1 = (const float*)d_in[6];
    const float* w2 = (const float*)d_in[7];
    const float* b2 = (const float*)d_in[8];
    float* out = (float*)d_out;

    const int smem = (18432 + 33024 + 32) * 4;  // 205,952 B
    cudaFuncSetAttribute(conv_mma<0>, cudaFuncAttributeMaxDynamicSharedMemorySize, smem);
    cudaFuncSetAttribute(conv_mma<1>, cudaFuncAttributeMaxDynamicSharedMemorySize, smem);

    setup_kernel<<<1, 256>>>(extrinsics, w1, w2);
    proj_kernel<<<dim3(256, 12), 256>>>(means, intrinsics);
    fuse_kernel<<<dim3(1024, 8), 256>>>(gs_feats);
    conv_mma<0><<<144, 512, smem>>>(b1, out);
    conv_mma<1><<<144, 512, smem>>>(b2, out);
}